// round 7
// baseline (speedup 1.0000x reference)
#include <cuda_runtime.h>
#include <cuda_bf16.h>

// Output of reference = minimum(y, 0.25) then clip(0.25, 1.0) == 0.25 everywhere,
// independent of inputs. Pure constant fill -> DRAM/L2 write-path bound.
//
// R7: final knob. Blocked layout (R3/R6 winner) + .cs streaming + 256-bit
// stores (.v8.b32, native on sm_100+). Bytes fixed at 244 MB; this halves STG
// instruction/wavefront-issue count per byte, targeting the L1tex path that
// ncu shows as the highest-utilization unit (71.8%). Evidence so far puts the
// write floor at ~5.5 TB/s; expected gain is small (~3%) or zero.

#define MIN_VALUE 0.25f
#define UNROLL 8
#define THREADS 256
// 32-byte (v8) chunks per CTA: 256 * 8 = 2048 -> 64 KB per CTA
#define PER_CTA ((long long)THREADS * UNROLL)

__device__ __forceinline__ void st256_cs(float* p, float f) {
    unsigned v = __float_as_uint(f);
    asm volatile("st.global.cs.v8.b32 [%0], {%1,%1,%1,%1,%1,%1,%1,%1};"
                 :: "l"(p), "r"(v) : "memory");
}

// n8 = number of 8-float (32-byte) chunks
__global__ void __launch_bounds__(THREADS) fill_const_blocked_v8(float* __restrict__ out,
                                                                 long long n8) {
    long long base = (long long)blockIdx.x * PER_CTA + threadIdx.x;

#pragma unroll
    for (int j = 0; j < UNROLL; j++) {
        long long i = base + (long long)j * THREADS;
        if (i < n8) {
            st256_cs(out + i * 8, MIN_VALUE);
        }
    }
}

__global__ void fill_const_tail(float* __restrict__ out, long long start, long long n) {
    long long i = start + (long long)blockIdx.x * blockDim.x + threadIdx.x;
    if (i < n) {
        out[i] = MIN_VALUE;
    }
}

extern "C" void kernel_launch(void* const* d_in, const int* in_sizes, int n_in,
                              void* d_out, int out_size) {
    (void)d_in; (void)in_sizes; (void)n_in;

    long long n = (long long)out_size;
    long long n8 = n >> 3;              // 32-byte chunks
    long long tail_start = n8 << 3;

    if (n8 > 0) {
        long long blocks = (n8 + PER_CTA - 1) / PER_CTA;
        fill_const_blocked_v8<<<(unsigned int)blocks, THREADS>>>((float*)d_out, n8);
    }
    if (tail_start < n) {
        long long tail = n - tail_start;
        long long blocks = (tail + THREADS - 1) / THREADS;
        fill_const_tail<<<(unsigned int)blocks, THREADS>>>((float*)d_out, tail_start, n);
    }
}

// round 8
// speedup vs baseline: 1.0494x; 1.0494x over previous
#include <cuda_runtime.h>
#include <cuda_bf16.h>

// Output of reference = minimum(y, 0.25) then clip(0.25, 1.0) == 0.25 everywhere,
// independent of inputs (all finite). Pure constant fill.
//
// FINAL (R8 = R1): steady-state analysis across R1-R7 shows the bench is paced
// by L2->DRAM dirty-line drain at ~6.6 TB/s (244 MB / ~37 us = 82% of spec HBM,
// the pure-write-stream ceiling). Kernel-side structure (occupancy 24-88%,
// MLP 1-8, .cs/default, 128/256-bit stores) does not move bench time; all
// variants converge to ~37 us. L2-persistence byte reduction is closed off by
// the harness device-limit guard; state-dependent skip-stores violate the
// determinism contract. R1 (one 128-bit store per thread, globally sequential
// address order) is the best-measured variant and is kept as final.

#define MIN_VALUE 0.25f

__global__ void fill_const_vec4(float4* __restrict__ out4, long long n4) {
    long long i = (long long)blockIdx.x * blockDim.x + threadIdx.x;
    if (i < n4) {
        out4[i] = make_float4(MIN_VALUE, MIN_VALUE, MIN_VALUE, MIN_VALUE);
    }
}

__global__ void fill_const_tail(float* __restrict__ out, long long start, long long n) {
    long long i = start + (long long)blockIdx.x * blockDim.x + threadIdx.x;
    if (i < n) {
        out[i] = MIN_VALUE;
    }
}

extern "C" void kernel_launch(void* const* d_in, const int* in_sizes, int n_in,
                              void* d_out, int out_size) {
    (void)d_in; (void)in_sizes; (void)n_in;

    long long n = (long long)out_size;
    long long n4 = n >> 2;              // number of float4 stores
    long long tail_start = n4 << 2;

    const int threads = 256;

    if (n4 > 0) {
        long long blocks = (n4 + threads - 1) / threads;
        fill_const_vec4<<<(unsigned int)blocks, threads>>>((float4*)d_out, n4);
    }
    if (tail_start < n) {
        long long tail = n - tail_start;
        long long blocks = (tail + threads - 1) / threads;
        fill_const_tail<<<(unsigned int)blocks, threads>>>((float*)d_out, tail_start, n);
    }
}